// round 4
// baseline (speedup 1.0000x reference)
#include <cuda_runtime.h>

#define N_USERS_C 200000
#define N_ITEMS_C 200000
#define NTOT      400000
#define DIM       64
#define NNZ_E     12800000
#define NLAYERS   3
#define CHUNKS    (NTOT / 64)

// Scratch: ping-pong ego buffers + side accumulator (allocation-free rule -> device globals)
__device__ float g_ego[2][(size_t)NTOT * DIM];
__device__ float g_side[(size_t)NTOT * DIM];

// ---------------------------------------------------------------------------
// Init: ego0 = concat(user_emb, item_emb); also write layer-0 columns of out.
// ---------------------------------------------------------------------------
__global__ void init_kernel(const float* __restrict__ ue,
                            const float* __restrict__ ie,
                            float* __restrict__ out) {
    int idx = blockIdx.x * blockDim.x + threadIdx.x;
    if (idx >= NTOT * DIM) return;
    int node = idx >> 6;
    int d = idx & 63;
    float v = (node < N_USERS_C) ? ue[idx] : ie[idx - N_USERS_C * DIM];
    g_ego[0][idx] = v;
    out[(size_t)node * 256 + d] = v;
}

__global__ void zero_side_kernel() {
    int idx = blockIdx.x * blockDim.x + threadIdx.x;
    if (idx < NTOT * DIM / 4) {
        ((float4*)g_side)[idx] = make_float4(0.f, 0.f, 0.f, 0.f);
    }
}

// ---------------------------------------------------------------------------
// SpMM: side[row] += vals[e] * ego[col], edge-parallel, 16 threads/edge,
// vectorized L2 reductions (red.global.add.v4.f32).
// ---------------------------------------------------------------------------
__global__ void spmm_kernel(const int* __restrict__ rows,
                            const int* __restrict__ cols,
                            const float* __restrict__ vals,
                            int pp) {
    int tid = blockIdx.x * blockDim.x + threadIdx.x;
    int e = tid >> 4;
    if (e >= NNZ_E) return;
    int j = tid & 15;
    int r = __ldg(rows + e);
    int c = __ldg(cols + e);
    float v = __ldg(vals + e);
    const float4* x4 = (const float4*)g_ego[pp];
    float4 g = __ldg(x4 + c * 16 + j);
    float* dst = g_side + (size_t)r * DIM + j * 4;
    asm volatile("red.global.add.v4.f32 [%0], {%1,%2,%3,%4};"
                 :: "l"(dst), "f"(g.x * v), "f"(g.y * v), "f"(g.z * v), "f"(g.w * v)
                 : "memory");
}

// ---------------------------------------------------------------------------
// Fused dense layer:
//   gc  = leaky_relu(side @ GcW^T + gc_b)
//   bi  = leaky_relu((ego*side) @ BiW^T + bi_b)
//   ego_next = gc + bi                      (unnormalized, feeds next layer)
//   out[:, off:off+64] = ego_next / max(||ego_next||_2, 1e-12)
// Block = 256 threads; each chunk = 64 nodes; thread tile = 4 nodes x 4 dims.
// Weights stored transposed in smem (wT[k][d]); side/prod padded stride 68.
// ---------------------------------------------------------------------------
__global__ void dense_kernel(const float* __restrict__ gw,
                             const float* __restrict__ gb,
                             const float* __restrict__ bw,
                             const float* __restrict__ bb,
                             float* __restrict__ out,
                             int col_off, int pp) {
    extern __shared__ float sh[];
    float* s_wgc  = sh;                 // 4096 floats, wT[k*64+d]
    float* s_wbi  = sh + 4096;          // 4096 floats
    float* s_side = sh + 8192;          // 64 * 68 = 4352 floats
    float* s_prod = sh + 8192 + 4352;   // 64 * 68 = 4352 floats (reused as e-buffer)

    const float* ego = g_ego[pp];
    float* ego_next  = g_ego[pp ^ 1];

    int t = threadIdx.x;

    // Load transposed weights once per block
    for (int idx = t; idx < 4096; idx += 256) {
        int d = idx & 63, k = idx >> 6;
        s_wgc[k * 64 + d] = gw[d * 64 + k];
        s_wbi[k * 64 + d] = bw[d * 64 + k];
    }

    const int d0 = (t & 15) * 4;   // this thread's 4 output dims
    const int n0 = (t >> 4) * 4;   // this thread's 4 nodes (within chunk)
    float bg[4], bbv[4];
#pragma unroll
    for (int j = 0; j < 4; j++) {
        bg[j]  = __ldg(gb + d0 + j);
        bbv[j] = __ldg(bb + d0 + j);
    }

    for (int c = blockIdx.x; c < CHUNKS; c += gridDim.x) {
        __syncthreads();  // previous chunk's readers done (also covers weight load, iter 0)
        int base = c * 64;

        // Stage side & ego*side tiles
        for (int idx = t; idx < 4096; idx += 256) {
            int node = idx >> 6, k = idx & 63;
            float sv = g_side[(size_t)(base + node) * 64 + k];
            float ev = ego[(size_t)(base + node) * 64 + k];
            s_side[node * 68 + k] = sv;
            s_prod[node * 68 + k] = sv * ev;
        }
        __syncthreads();

        float accg[4][4], accb[4][4];
#pragma unroll
        for (int i = 0; i < 4; i++)
#pragma unroll
            for (int j = 0; j < 4; j++) {
                accg[i][j] = bg[j];
                accb[i][j] = bbv[j];
            }

#pragma unroll 8
        for (int k = 0; k < 64; k++) {
            float4 wg = *(const float4*)&s_wgc[k * 64 + d0];
            float4 wb = *(const float4*)&s_wbi[k * 64 + d0];
            float sv[4], pv[4];
#pragma unroll
            for (int i = 0; i < 4; i++) {
                sv[i] = s_side[(n0 + i) * 68 + k];
                pv[i] = s_prod[(n0 + i) * 68 + k];
            }
#pragma unroll
            for (int i = 0; i < 4; i++) {
                accg[i][0] += sv[i] * wg.x;
                accg[i][1] += sv[i] * wg.y;
                accg[i][2] += sv[i] * wg.z;
                accg[i][3] += sv[i] * wg.w;
                accb[i][0] += pv[i] * wb.x;
                accb[i][1] += pv[i] * wb.y;
                accb[i][2] += pv[i] * wb.z;
                accb[i][3] += pv[i] * wb.w;
            }
        }
        __syncthreads();  // all compute reads of s_prod done before overwrite

        // e = lrelu(gc) + lrelu(bi) into smem (reuse s_prod)
#pragma unroll
        for (int i = 0; i < 4; i++)
#pragma unroll
            for (int j = 0; j < 4; j++) {
                float a = accg[i][j], b = accb[i][j];
                float e = fmaxf(a, 0.01f * a) + fmaxf(b, 0.01f * b);
                s_prod[(n0 + i) * 68 + d0 + j] = e;
            }
        __syncthreads();

        // Row norms + global writes: thread -> (node = t/4, quarter q = t%4)
        int node = t >> 2, q = t & 3;
        float ss = 0.f;
#pragma unroll
        for (int m = 0; m < 16; m++) {
            float v = s_prod[node * 68 + q * 16 + m];
            ss += v * v;
        }
        ss += __shfl_xor_sync(0xffffffffu, ss, 1);
        ss += __shfl_xor_sync(0xffffffffu, ss, 2);
        float inv = 1.f / fmaxf(sqrtf(ss), 1e-12f);

        size_t gnode = (size_t)(base + node);
#pragma unroll
        for (int m = 0; m < 16; m += 4) {
            float4 v = *(const float4*)&s_prod[node * 68 + q * 16 + m];
            *(float4*)&ego_next[gnode * 64 + q * 16 + m] = v;
            float4 vn = make_float4(v.x * inv, v.y * inv, v.z * inv, v.w * inv);
            *(float4*)&out[gnode * 256 + col_off + q * 16 + m] = vn;
        }
    }
}

// ---------------------------------------------------------------------------
extern "C" void kernel_launch(void* const* d_in, const int* in_sizes, int n_in,
                              void* d_out, int out_size) {
    const int*   rows = (const int*)d_in[0];
    const int*   cols = (const int*)d_in[1];
    const float* vals = (const float*)d_in[2];
    const float* ue   = (const float*)d_in[3];
    const float* ie   = (const float*)d_in[4];
    const float* gw   = (const float*)d_in[5];
    const float* gb   = (const float*)d_in[6];
    const float* bw   = (const float*)d_in[7];
    const float* bb   = (const float*)d_in[8];
    float* out = (float*)d_out;

    const int smem_bytes = (4096 * 2 + 4352 * 2) * 4;  // 67584 B
    cudaFuncSetAttribute(dense_kernel,
                         cudaFuncAttributeMaxDynamicSharedMemorySize, smem_bytes);

    init_kernel<<<(NTOT * DIM + 255) / 256, 256>>>(ue, ie, out);

    for (int i = 0; i < NLAYERS; i++) {
        int pp = i & 1;  // read g_ego[pp], write g_ego[pp^1]
        zero_side_kernel<<<(NTOT * DIM / 4 + 255) / 256, 256>>>();
        spmm_kernel<<<(NNZ_E * 16) / 256, 256>>>(rows, cols, vals, pp);
        dense_kernel<<<444, 256, smem_bytes>>>(gw + i * 4096, gb + i * 64,
                                               bw + i * 4096, bb + i * 64,
                                               out, (i + 1) * 64, pp);
    }
}

// round 8
// speedup vs baseline: 1.3859x; 1.3859x over previous
#include <cuda_runtime.h>

#define N_USERS_C 200000
#define NTOT      400000
#define DIM       64
#define NNZ_E     12800000
#define NLAYERS   3
#define CHUNKS    (NTOT / 64)
#define NB_SCAN   ((NTOT + 1023) / 1024)   // 391

// ---- device-global scratch (allocation-free rule) ----
__device__ float g_ego[2][(size_t)NTOT * DIM];
__device__ int   g_cnt[NTOT];
__device__ int   g_scan[NTOT];
__device__ int   g_rp[NTOT + 1];
__device__ int   g_cur[NTOT];
__device__ int   g_bsum[NB_SCAN];
__device__ int   g_boff[NB_SCAN];
__device__ int   g_cs[NNZ_E];
__device__ float g_vs[NNZ_E];

// ---------------------------------------------------------------------------
__global__ void init_kernel(const float* __restrict__ ue,
                            const float* __restrict__ ie,
                            float* __restrict__ out) {
    int idx = blockIdx.x * blockDim.x + threadIdx.x;
    if (idx >= NTOT * DIM) return;
    int node = idx >> 6;
    int d = idx & 63;
    float v = (node < N_USERS_C) ? ue[idx] : ie[idx - N_USERS_C * DIM];
    g_ego[0][idx] = v;
    out[(size_t)node * 256 + d] = v;
}

__global__ void zero_cnt_kernel() {
    int i = blockIdx.x * blockDim.x + threadIdx.x;
    if (i < NTOT) g_cnt[i] = 0;
}

__global__ void hist_kernel(const int* __restrict__ rows) {
    int e = blockIdx.x * blockDim.x + threadIdx.x;
    if (e < NNZ_E) atomicAdd(&g_cnt[__ldg(rows + e)], 1);
}

// Per-block exclusive scan of 1024 counts; block total to g_bsum.
__global__ void scan_local_kernel() {
    __shared__ int wsum[8];
    int b = blockIdx.x, t = threadIdx.x;
    int base = b * 1024 + t * 4;
    int v0 = 0, v1 = 0, v2 = 0, v3 = 0;
    if (base + 0 < NTOT) v0 = g_cnt[base + 0];
    if (base + 1 < NTOT) v1 = g_cnt[base + 1];
    if (base + 2 < NTOT) v2 = g_cnt[base + 2];
    if (base + 3 < NTOT) v3 = g_cnt[base + 3];
    int tsum = v0 + v1 + v2 + v3;
    int lane = t & 31, w = t >> 5;
    int x = tsum;
#pragma unroll
    for (int d = 1; d < 32; d <<= 1) {
        int y = __shfl_up_sync(0xffffffffu, x, d);
        if (lane >= d) x += y;
    }
    if (lane == 31) wsum[w] = x;
    __syncthreads();
    if (t < 8) {
        int y = wsum[t];
#pragma unroll
        for (int d = 1; d < 8; d <<= 1) {
            int z = __shfl_up_sync(0xffu, y, d, 8);
            if (t >= d) y += z;
        }
        wsum[t] = y;
    }
    __syncthreads();
    int woff = (w == 0) ? 0 : wsum[w - 1];
    int ex = woff + x - tsum;
    if (base + 0 < NTOT) g_scan[base + 0] = ex;
    ex += v0;
    if (base + 1 < NTOT) g_scan[base + 1] = ex;
    ex += v1;
    if (base + 2 < NTOT) g_scan[base + 2] = ex;
    ex += v2;
    if (base + 3 < NTOT) g_scan[base + 3] = ex;
    if (t == 0) g_bsum[b] = wsum[7];
}

// Exclusive scan of the NB_SCAN block sums (single block of 512).
__global__ void scan_block_kernel() {
    __shared__ int wsum[16];
    int t = threadIdx.x;
    int v = (t < NB_SCAN) ? g_bsum[t] : 0;
    int lane = t & 31, w = t >> 5;
    int x = v;
#pragma unroll
    for (int d = 1; d < 32; d <<= 1) {
        int y = __shfl_up_sync(0xffffffffu, x, d);
        if (lane >= d) x += y;
    }
    if (lane == 31) wsum[w] = x;
    __syncthreads();
    if (t < 16) {
        int y = wsum[t];
#pragma unroll
        for (int d = 1; d < 16; d <<= 1) {
            int z = __shfl_up_sync(0xffffu, y, d, 16);
            if (t >= d) y += z;
        }
        wsum[t] = y;
    }
    __syncthreads();
    int woff = (w == 0) ? 0 : wsum[w - 1];
    if (t < NB_SCAN) g_boff[t] = woff + x - v;
}

__global__ void scan_finish_kernel() {
    int i = blockIdx.x * blockDim.x + threadIdx.x;
    if (i < NTOT) {
        int r = g_scan[i] + g_boff[i >> 10];
        g_rp[i] = r;
        g_cur[i] = r;
    }
    if (i == 0) g_rp[NTOT] = NNZ_E;
}

__global__ void scatter_kernel(const int* __restrict__ rows,
                               const int* __restrict__ cols,
                               const float* __restrict__ vals) {
    int e = blockIdx.x * blockDim.x + threadIdx.x;
    if (e >= NNZ_E) return;
    int r = __ldg(rows + e);
    int pos = atomicAdd(&g_cur[r], 1);
    g_cs[pos] = __ldg(cols + e);
    g_vs[pos] = __ldg(vals + e);
}

// ---------------------------------------------------------------------------
// Fused layer: CSR SpMM (no atomics) -> smem tiles -> GC/Bi GEMM + lrelu +
// row-L2-normalize -> out columns + next ego.
// Block = 256 threads = 16 half-warps; chunk = 64 rows; half-warp h owns rows
// h*4..h*4+3; lane j owns dims [4j, 4j+4).
// ---------------------------------------------------------------------------
__global__ void __launch_bounds__(256)
fused_layer_kernel(const float* __restrict__ gw,
                   const float* __restrict__ gb,
                   const float* __restrict__ bw,
                   const float* __restrict__ bb,
                   float* __restrict__ out,
                   int col_off, int pp) {
    extern __shared__ float sh[];
    float* s_wgc  = sh;                 // 4096: wT[k*64+d]
    float* s_wbi  = sh + 4096;          // 4096
    float* s_side = sh + 8192;          // 64*68
    float* s_prod = sh + 8192 + 4352;   // 64*68 (reused as e-buffer)

    const float*  ego = g_ego[pp];
    float*   ego_next = g_ego[pp ^ 1];
    const float4* x4  = (const float4*)ego;

    int t = threadIdx.x;
    int j = t & 15;                         // lane within half-warp
    int h = t >> 4;                         // half-warp id (0..15)
    unsigned hmask = 0xFFFFu << (t & 16);   // own half-warp's mask

    for (int idx = t; idx < 4096; idx += 256) {
        int d = idx & 63, k = idx >> 6;
        s_wgc[k * 64 + d] = gw[d * 64 + k];
        s_wbi[k * 64 + d] = bw[d * 64 + k];
    }

    const int d0 = (t & 15) * 4;
    const int n0 = (t >> 4) * 4;
    float bg[4], bbv[4];
#pragma unroll
    for (int q = 0; q < 4; q++) {
        bg[q]  = __ldg(gb + d0 + q);
        bbv[q] = __ldg(bb + d0 + q);
    }

    for (int c = blockIdx.x; c < CHUNKS; c += gridDim.x) {
        __syncthreads();
        int base = c * 64;

        // ---- Phase 1: CSR SpMM into smem (4 rows per half-warp) ----
#pragma unroll
        for (int i = 0; i < 4; i++) {
            int r = base + h * 4 + i;
            int s = __ldg(g_rp + r), e = __ldg(g_rp + r + 1);
            float4 acc = make_float4(0.f, 0.f, 0.f, 0.f);
            for (int p = s; p < e; p += 16) {
                int idx = p + j;
                int cj = -1; float vj = 0.f;
                if (idx < e) { cj = g_cs[idx]; vj = g_vs[idx]; }
#pragma unroll
                for (int q = 0; q < 16; q++) {
                    int cc   = __shfl_sync(hmask, cj, q, 16);
                    float vv = __shfl_sync(hmask, vj, q, 16);
                    if (cc >= 0) {
                        float4 g4 = __ldg(x4 + (size_t)cc * 16 + j);
                        acc.x += vv * g4.x;
                        acc.y += vv * g4.y;
                        acc.z += vv * g4.z;
                        acc.w += vv * g4.w;
                    }
                }
            }
            float4 ev = __ldg(x4 + (size_t)r * 16 + j);
            int node = h * 4 + i;
            *(float4*)&s_side[node * 68 + j * 4] = acc;
            *(float4*)&s_prod[node * 68 + j * 4] =
                make_float4(acc.x * ev.x, acc.y * ev.y, acc.z * ev.z, acc.w * ev.w);
        }
        __syncthreads();

        // ---- Phase 2: dense GC/Bi GEMM (4 nodes x 4 dims per thread) ----
        float accg[4][4], accb[4][4];
#pragma unroll
        for (int i = 0; i < 4; i++)
#pragma unroll
            for (int q = 0; q < 4; q++) {
                accg[i][q] = bg[q];
                accb[i][q] = bbv[q];
            }

#pragma unroll 8
        for (int k = 0; k < 64; k++) {
            float4 wg = *(const float4*)&s_wgc[k * 64 + d0];
            float4 wb = *(const float4*)&s_wbi[k * 64 + d0];
            float sv[4], pv[4];
#pragma unroll
            for (int i = 0; i < 4; i++) {
                sv[i] = s_side[(n0 + i) * 68 + k];
                pv[i] = s_prod[(n0 + i) * 68 + k];
            }
#pragma unroll
            for (int i = 0; i < 4; i++) {
                accg[i][0] += sv[i] * wg.x;
                accg[i][1] += sv[i] * wg.y;
                accg[i][2] += sv[i] * wg.z;
                accg[i][3] += sv[i] * wg.w;
                accb[i][0] += pv[i] * wb.x;
                accb[i][1] += pv[i] * wb.y;
                accb[i][2] += pv[i] * wb.z;
                accb[i][3] += pv[i] * wb.w;
            }
        }
        __syncthreads();

        // e = lrelu(gc) + lrelu(bi) into smem (reuse s_prod)
#pragma unroll
        for (int i = 0; i < 4; i++)
#pragma unroll
            for (int q = 0; q < 4; q++) {
                float a = accg[i][q], b = accb[i][q];
                float e = fmaxf(a, 0.01f * a) + fmaxf(b, 0.01f * b);
                s_prod[(n0 + i) * 68 + d0 + q] = e;
            }
        __syncthreads();

        // Row norms + global writes: thread -> (node = t/4, quarter = t%4)
        int node = t >> 2, qq = t & 3;
        float ss = 0.f;
#pragma unroll
        for (int m = 0; m < 16; m++) {
            float v = s_prod[node * 68 + qq * 16 + m];
            ss += v * v;
        }
        ss += __shfl_xor_sync(0xffffffffu, ss, 1);
        ss += __shfl_xor_sync(0xffffffffu, ss, 2);
        float inv = 1.f / fmaxf(sqrtf(ss), 1e-12f);

        size_t gnode = (size_t)(base + node);
#pragma unroll
        for (int m = 0; m < 16; m += 4) {
            float4 v = *(const float4*)&s_prod[node * 68 + qq * 16 + m];
            *(float4*)&ego_next[gnode * 64 + qq * 16 + m] = v;
            float4 vn = make_float4(v.x * inv, v.y * inv, v.z * inv, v.w * inv);
            *(float4*)&out[gnode * 256 + col_off + qq * 16 + m] = vn;
        }
    }
}

// ---------------------------------------------------------------------------
extern "C" void kernel_launch(void* const* d_in, const int* in_sizes, int n_in,
                              void* d_out, int out_size) {
    const int*   rows = (const int*)d_in[0];
    const int*   cols = (const int*)d_in[1];
    const float* vals = (const float*)d_in[2];
    const float* ue   = (const float*)d_in[3];
    const float* ie   = (const float*)d_in[4];
    const float* gw   = (const float*)d_in[5];
    const float* gb   = (const float*)d_in[6];
    const float* bw   = (const float*)d_in[7];
    const float* bb   = (const float*)d_in[8];
    float* out = (float*)d_out;

    const int smem_bytes = (4096 * 2 + 4352 * 2) * 4;  // 67584 B
    cudaFuncSetAttribute(fused_layer_kernel,
                         cudaFuncAttributeMaxDynamicSharedMemorySize, smem_bytes);

    init_kernel<<<(NTOT * DIM + 255) / 256, 256>>>(ue, ie, out);

    // ---- CSR build (once; reused by all 3 layers) ----
    zero_cnt_kernel<<<(NTOT + 255) / 256, 256>>>();
    hist_kernel<<<(NNZ_E + 255) / 256, 256>>>(rows);
    scan_local_kernel<<<NB_SCAN, 256>>>();
    scan_block_kernel<<<1, 512>>>();
    scan_finish_kernel<<<(NTOT + 255) / 256, 256>>>();
    scatter_kernel<<<(NNZ_E + 255) / 256, 256>>>(rows, cols, vals);

    // ---- 3 fused layers ----
    for (int i = 0; i < NLAYERS; i++) {
        int pp = i & 1;
        fused_layer_kernel<<<CHUNKS, 256, smem_bytes>>>(
            gw + i * 4096, gb + i * 64, bw + i * 4096, bb + i * 64,
            out, (i + 1) * 64, pp);
    }
}

// round 9
// speedup vs baseline: 1.6243x; 1.1720x over previous
#include <cuda_runtime.h>

#define N_USERS_C 200000
#define NTOT      400000
#define DIM       64
#define NNZ_E     12800000
#define NLAYERS   3
#define CHUNKS    (NTOT / 64)

#define NTILES    3
#define TILE1     133334
#define TILE2     266668
#define NSEG      (NTOT * NTILES)            // 1,200,000
#define NB2       ((NSEG + 4095) / 4096)     // 293

// ---- device-global scratch (allocation-free rule) ----
__device__ float g_ego[2][(size_t)NTOT * DIM];
__device__ float g_side[(size_t)NTOT * DIM];
__device__ int   g_cnt[NSEG];
__device__ int   g_scan[NSEG];
__device__ int   g_rp2[NSEG + 1];
__device__ int   g_cur[NSEG];
__device__ int   g_bsum[NB2];
__device__ int   g_boff[NB2];
__device__ int2  g_csv[NNZ_E];               // (col, float-bits of val)

// ---------------------------------------------------------------------------
__global__ void init_kernel(const float* __restrict__ ue,
                            const float* __restrict__ ie,
                            float* __restrict__ out) {
    int idx = blockIdx.x * blockDim.x + threadIdx.x;
    if (idx >= NTOT * DIM) return;
    int node = idx >> 6;
    int d = idx & 63;
    float v = (node < N_USERS_C) ? ue[idx] : ie[idx - N_USERS_C * DIM];
    g_ego[0][idx] = v;
    out[(size_t)node * 256 + d] = v;
}

__global__ void zero_cnt_kernel() {
    int i = blockIdx.x * blockDim.x + threadIdx.x;
    if (i < NSEG) g_cnt[i] = 0;
}

__global__ void hist_kernel(const int* __restrict__ rows,
                            const int* __restrict__ cols) {
    int e = blockIdx.x * blockDim.x + threadIdx.x;
    if (e >= NNZ_E) return;
    int r = __ldg(rows + e);
    int c = __ldg(cols + e);
    int t = (c >= TILE1) + (c >= TILE2);
    atomicAdd(&g_cnt[r * NTILES + t], 1);
}

// Per-block exclusive scan of 4096 counts (1024 thr x 4); block total to g_bsum.
__global__ void scan_local_kernel() {
    __shared__ int wsum[32];
    int b = blockIdx.x, t = threadIdx.x;
    int base = b * 4096 + t * 4;
    int v0 = 0, v1 = 0, v2 = 0, v3 = 0;
    if (base + 0 < NSEG) v0 = g_cnt[base + 0];
    if (base + 1 < NSEG) v1 = g_cnt[base + 1];
    if (base + 2 < NSEG) v2 = g_cnt[base + 2];
    if (base + 3 < NSEG) v3 = g_cnt[base + 3];
    int tsum = v0 + v1 + v2 + v3;
    int lane = t & 31, w = t >> 5;
    int x = tsum;
#pragma unroll
    for (int d = 1; d < 32; d <<= 1) {
        int y = __shfl_up_sync(0xffffffffu, x, d);
        if (lane >= d) x += y;
    }
    if (lane == 31) wsum[w] = x;
    __syncthreads();
    if (t < 32) {
        int y = wsum[t];
#pragma unroll
        for (int d = 1; d < 32; d <<= 1) {
            int z = __shfl_up_sync(0xffffffffu, y, d);
            if (t >= d) y += z;
        }
        wsum[t] = y;
    }
    __syncthreads();
    int woff = (w == 0) ? 0 : wsum[w - 1];
    int ex = woff + x - tsum;
    if (base + 0 < NSEG) g_scan[base + 0] = ex;
    ex += v0;
    if (base + 1 < NSEG) g_scan[base + 1] = ex;
    ex += v1;
    if (base + 2 < NSEG) g_scan[base + 2] = ex;
    ex += v2;
    if (base + 3 < NSEG) g_scan[base + 3] = ex;
    if (t == 0) g_bsum[b] = wsum[31];
}

// Exclusive scan of the NB2 block sums (single block of 512).
__global__ void scan_block_kernel() {
    __shared__ int wsum[16];
    int t = threadIdx.x;
    int v = (t < NB2) ? g_bsum[t] : 0;
    int lane = t & 31, w = t >> 5;
    int x = v;
#pragma unroll
    for (int d = 1; d < 32; d <<= 1) {
        int y = __shfl_up_sync(0xffffffffu, x, d);
        if (lane >= d) x += y;
    }
    if (lane == 31) wsum[w] = x;
    __syncthreads();
    if (t < 16) {
        int y = wsum[t];
#pragma unroll
        for (int d = 1; d < 16; d <<= 1) {
            int z = __shfl_up_sync(0xffffu, y, d, 16);
            if (t >= d) y += z;
        }
        wsum[t] = y;
    }
    __syncthreads();
    int woff = (w == 0) ? 0 : wsum[w - 1];
    if (t < NB2) g_boff[t] = woff + x - v;
}

__global__ void scan_finish_kernel() {
    int i = blockIdx.x * blockDim.x + threadIdx.x;
    if (i < NSEG) {
        int r = g_scan[i] + g_boff[i >> 12];
        g_rp2[i] = r;
        g_cur[i] = r;
    }
    if (i == 0) g_rp2[NSEG] = NNZ_E;
}

__global__ void scatter_kernel(const int* __restrict__ rows,
                               const int* __restrict__ cols,
                               const float* __restrict__ vals) {
    int e = blockIdx.x * blockDim.x + threadIdx.x;
    if (e >= NNZ_E) return;
    int r = __ldg(rows + e);
    int c = __ldg(cols + e);
    float v = __ldg(vals + e);
    int t = (c >= TILE1) + (c >= TILE2);
    int pos = atomicAdd(&g_cur[r * NTILES + t], 1);
    g_csv[pos] = make_int2(c, __float_as_int(v));
}

// ---------------------------------------------------------------------------
// SpMM pass over one column tile: half-warp per row, exclusive ownership,
// accumulates into g_side (write on first pass, RMW afterwards).
// All concurrent blocks touch only this tile's ~34MB ego slice -> L2 resident.
// ---------------------------------------------------------------------------
__global__ void __launch_bounds__(256)
spmm_pass_kernel(int tile, int first, int pp) {
    int gtid = blockIdx.x * blockDim.x + threadIdx.x;
    int r = gtid >> 4;
    if (r >= NTOT) return;
    int j = threadIdx.x & 15;
    unsigned hmask = 0xFFFFu << (threadIdx.x & 16);

    const float4* x4 = (const float4*)g_ego[pp];
    float4* side4 = (float4*)g_side;

    int s = __ldg(g_rp2 + r * NTILES + tile);
    int e = __ldg(g_rp2 + r * NTILES + tile + 1);

    float4 acc;
    if (first) acc = make_float4(0.f, 0.f, 0.f, 0.f);
    else       acc = __ldg(side4 + (size_t)r * 16 + j);

    for (int p = s; p < e; p += 16) {
        int idx = p + j;
        int cj = -1; float vj = 0.f;
        if (idx < e) {
            int2 cv = __ldg(g_csv + idx);
            cj = cv.x; vj = __int_as_float(cv.y);
        }
#pragma unroll
        for (int q = 0; q < 16; q++) {
            int cc   = __shfl_sync(hmask, cj, q, 16);
            float vv = __shfl_sync(hmask, vj, q, 16);
            if (cc >= 0) {
                float4 g4 = __ldg(x4 + (size_t)cc * 16 + j);
                acc.x += vv * g4.x;
                acc.y += vv * g4.y;
                acc.z += vv * g4.z;
                acc.w += vv * g4.w;
            }
        }
    }
    side4[(size_t)r * 16 + j] = acc;
}

// ---------------------------------------------------------------------------
// Fused: last tile's SpMM (seeded with g_side partial) -> smem tiles ->
// GC/Bi GEMM + lrelu + row-L2-normalize -> out columns + next ego.
// ---------------------------------------------------------------------------
__global__ void __launch_bounds__(256)
fused_layer_kernel(const float* __restrict__ gw,
                   const float* __restrict__ gb,
                   const float* __restrict__ bw,
                   const float* __restrict__ bb,
                   float* __restrict__ out,
                   int col_off, int pp) {
    extern __shared__ float sh[];
    float* s_wgc  = sh;                 // 4096: wT[k*64+d]
    float* s_wbi  = sh + 4096;          // 4096
    float* s_side = sh + 8192;          // 64*68
    float* s_prod = sh + 8192 + 4352;   // 64*68 (reused as e-buffer)

    const float*  ego = g_ego[pp];
    float*   ego_next = g_ego[pp ^ 1];
    const float4* x4  = (const float4*)ego;
    const float4* side4 = (const float4*)g_side;

    int t = threadIdx.x;
    int j = t & 15;
    int h = t >> 4;
    unsigned hmask = 0xFFFFu << (t & 16);

    for (int idx = t; idx < 4096; idx += 256) {
        int d = idx & 63, k = idx >> 6;
        s_wgc[k * 64 + d] = gw[d * 64 + k];
        s_wbi[k * 64 + d] = bw[d * 64 + k];
    }

    const int d0 = (t & 15) * 4;
    const int n0 = (t >> 4) * 4;
    float bg[4], bbv[4];
#pragma unroll
    for (int q = 0; q < 4; q++) {
        bg[q]  = __ldg(gb + d0 + q);
        bbv[q] = __ldg(bb + d0 + q);
    }

    for (int c = blockIdx.x; c < CHUNKS; c += gridDim.x) {
        __syncthreads();
        int base = c * 64;

        // ---- Phase 1: tile (NTILES-1) SpMM seeded with side partial ----
#pragma unroll
        for (int i = 0; i < 4; i++) {
            int r = base + h * 4 + i;
            int s = __ldg(g_rp2 + r * NTILES + (NTILES - 1));
            int e = __ldg(g_rp2 + r * NTILES + NTILES);
            float4 acc = __ldg(side4 + (size_t)r * 16 + j);
            for (int p = s; p < e; p += 16) {
                int idx = p + j;
                int cj = -1; float vj = 0.f;
                if (idx < e) {
                    int2 cv = __ldg(g_csv + idx);
                    cj = cv.x; vj = __int_as_float(cv.y);
                }
#pragma unroll
                for (int q = 0; q < 16; q++) {
                    int cc   = __shfl_sync(hmask, cj, q, 16);
                    float vv = __shfl_sync(hmask, vj, q, 16);
                    if (cc >= 0) {
                        float4 g4 = __ldg(x4 + (size_t)cc * 16 + j);
                        acc.x += vv * g4.x;
                        acc.y += vv * g4.y;
                        acc.z += vv * g4.z;
                        acc.w += vv * g4.w;
                    }
                }
            }
            float4 ev = __ldg(x4 + (size_t)r * 16 + j);
            int node = h * 4 + i;
            *(float4*)&s_side[node * 68 + j * 4] = acc;
            *(float4*)&s_prod[node * 68 + j * 4] =
                make_float4(acc.x * ev.x, acc.y * ev.y, acc.z * ev.z, acc.w * ev.w);
        }
        __syncthreads();

        // ---- Phase 2: dense GC/Bi GEMM (4 nodes x 4 dims per thread) ----
        float accg[4][4], accb[4][4];
#pragma unroll
        for (int i = 0; i < 4; i++)
#pragma unroll
            for (int q = 0; q < 4; q++) {
                accg[i][q] = bg[q];
                accb[i][q] = bbv[q];
            }

#pragma unroll 8
        for (int k = 0; k < 64; k++) {
            float4 wg = *(const float4*)&s_wgc[k * 64 + d0];
            float4 wb = *(const float4*)&s_wbi[k * 64 + d0];
            float sv[4], pv[4];
#pragma unroll
            for (int i = 0; i < 4; i++) {
                sv[i] = s_side[(n0 + i) * 68 + k];
                pv[i] = s_prod[(n0 + i) * 68 + k];
            }
#pragma unroll
            for (int i = 0; i < 4; i++) {
                accg[i][0] += sv[i] * wg.x;
                accg[i][1] += sv[i] * wg.y;
                accg[i][2] += sv[i] * wg.z;
                accg[i][3] += sv[i] * wg.w;
                accb[i][0] += pv[i] * wb.x;
                accb[i][1] += pv[i] * wb.y;
                accb[i][2] += pv[i] * wb.z;
                accb[i][3] += pv[i] * wb.w;
            }
        }
        __syncthreads();

        // e = lrelu(gc) + lrelu(bi) into smem (reuse s_prod)
#pragma unroll
        for (int i = 0; i < 4; i++)
#pragma unroll
            for (int q = 0; q < 4; q++) {
                float a = accg[i][q], b = accb[i][q];
                float e = fmaxf(a, 0.01f * a) + fmaxf(b, 0.01f * b);
                s_prod[(n0 + i) * 68 + d0 + q] = e;
            }
        __syncthreads();

        // Row norms + global writes: thread -> (node = t/4, quarter = t%4)
        int node = t >> 2, qq = t & 3;
        float ss = 0.f;
#pragma unroll
        for (int m = 0; m < 16; m++) {
            float v = s_prod[node * 68 + qq * 16 + m];
            ss += v * v;
        }
        ss += __shfl_xor_sync(0xffffffffu, ss, 1);
        ss += __shfl_xor_sync(0xffffffffu, ss, 2);
        float inv = 1.f / fmaxf(sqrtf(ss), 1e-12f);

        size_t gnode = (size_t)(base + node);
#pragma unroll
        for (int m = 0; m < 16; m += 4) {
            float4 v = *(const float4*)&s_prod[node * 68 + qq * 16 + m];
            *(float4*)&ego_next[gnode * 64 + qq * 16 + m] = v;
            float4 vn = make_float4(v.x * inv, v.y * inv, v.z * inv, v.w * inv);
            *(float4*)&out[gnode * 256 + col_off + qq * 16 + m] = vn;
        }
    }
}

// ---------------------------------------------------------------------------
extern "C" void kernel_launch(void* const* d_in, const int* in_sizes, int n_in,
                              void* d_out, int out_size) {
    const int*   rows = (const int*)d_in[0];
    const int*   cols = (const int*)d_in[1];
    const float* vals = (const float*)d_in[2];
    const float* ue   = (const float*)d_in[3];
    const float* ie   = (const float*)d_in[4];
    const float* gw   = (const float*)d_in[5];
    const float* gb   = (const float*)d_in[6];
    const float* bw   = (const float*)d_in[7];
    const float* bb   = (const float*)d_in[8];
    float* out = (float*)d_out;

    const int smem_bytes = (4096 * 2 + 4352 * 2) * 4;  // 67584 B
    cudaFuncSetAttribute(fused_layer_kernel,
                         cudaFuncAttributeMaxDynamicSharedMemorySize, smem_bytes);

    init_kernel<<<(NTOT * DIM + 255) / 256, 256>>>(ue, ie, out);

    // ---- (row, col-tile)-sorted edge list build (once; reused by all layers) ----
    zero_cnt_kernel<<<(NSEG + 255) / 256, 256>>>();
    hist_kernel<<<(NNZ_E + 255) / 256, 256>>>(rows, cols);
    scan_local_kernel<<<NB2, 1024>>>();
    scan_block_kernel<<<1, 512>>>();
    scan_finish_kernel<<<(NSEG + 255) / 256, 256>>>();
    scatter_kernel<<<(NNZ_E + 255) / 256, 256>>>(rows, cols, vals);

    // ---- 3 layers: 2 tile passes + fused(last tile + dense) ----
    const int pass_blocks = (NTOT * 16 + 255) / 256;  // one half-warp per row
    for (int i = 0; i < NLAYERS; i++) {
        int pp = i & 1;
        spmm_pass_kernel<<<pass_blocks, 256>>>(0, 1, pp);
        spmm_pass_kernel<<<pass_blocks, 256>>>(1, 0, pp);
        fused_layer_kernel<<<CHUNKS, 256, smem_bytes>>>(
            gw + i * 4096, gb + i * 64, bw + i * 4096, bb + i * 64,
            out, (i + 1) * 64, pp);
    }
}

// round 10
// speedup vs baseline: 1.6460x; 1.0133x over previous
#include <cuda_runtime.h>

#define N_USERS_C 200000
#define NTOT      400000
#define DIM       64
#define NNZ_E     12800000
#define NLAYERS   3
#define CHUNKS    (NTOT / 64)

#define NTILES    2
#define TSPLIT    200000
#define NSEG      (NTOT * NTILES)            // 800,000
#define NB2       ((NSEG + 4095) / 4096)     // 196

// ---- device-global scratch (allocation-free rule) ----
__device__ float g_ego[2][(size_t)NTOT * DIM];
__device__ float g_side[(size_t)NTOT * DIM];
__device__ int   g_cnt[NSEG];
__device__ int   g_scan[NSEG];
__device__ int   g_rp2[NSEG + 1];
__device__ int   g_cur[NSEG];
__device__ int   g_bsum[NB2];
__device__ int   g_boff[NB2];
__device__ int2  g_csv[NNZ_E];               // (col, float-bits of val)

// L2 evict-last policy + hinted 128-bit gather (keeps the hot ego slice pinned)
__device__ __forceinline__ unsigned long long mk_evict_last() {
    unsigned long long pol;
    asm("createpolicy.fractional.L2::evict_last.b64 %0, 1.0;" : "=l"(pol));
    return pol;
}
__device__ __forceinline__ float4 ldg_el(const float4* p, unsigned long long pol) {
    float4 r;
    asm volatile("ld.global.nc.L2::cache_hint.v4.f32 {%0,%1,%2,%3}, [%4], %5;"
                 : "=f"(r.x), "=f"(r.y), "=f"(r.z), "=f"(r.w)
                 : "l"(p), "l"(pol));
    return r;
}

// ---------------------------------------------------------------------------
__global__ void init_kernel(const float* __restrict__ ue,
                            const float* __restrict__ ie,
                            float* __restrict__ out) {
    int idx = blockIdx.x * blockDim.x + threadIdx.x;
    if (idx >= NTOT * DIM) return;
    int node = idx >> 6;
    int d = idx & 63;
    float v = (node < N_USERS_C) ? ue[idx] : ie[idx - N_USERS_C * DIM];
    g_ego[0][idx] = v;
    out[(size_t)node * 256 + d] = v;
}

__global__ void zero_cnt_kernel() {
    int i = blockIdx.x * blockDim.x + threadIdx.x;
    if (i < NSEG) g_cnt[i] = 0;
}

__global__ void hist_kernel(const int* __restrict__ rows,
                            const int* __restrict__ cols) {
    int e = blockIdx.x * blockDim.x + threadIdx.x;
    if (e >= NNZ_E) return;
    int r = __ldg(rows + e);
    int c = __ldg(cols + e);
    int t = (c >= TSPLIT);
    atomicAdd(&g_cnt[r * NTILES + t], 1);
}

// Per-block exclusive scan of 4096 counts (1024 thr x 4); block total to g_bsum.
__global__ void scan_local_kernel() {
    __shared__ int wsum[32];
    int b = blockIdx.x, t = threadIdx.x;
    int base = b * 4096 + t * 4;
    int v0 = 0, v1 = 0, v2 = 0, v3 = 0;
    if (base + 0 < NSEG) v0 = g_cnt[base + 0];
    if (base + 1 < NSEG) v1 = g_cnt[base + 1];
    if (base + 2 < NSEG) v2 = g_cnt[base + 2];
    if (base + 3 < NSEG) v3 = g_cnt[base + 3];
    int tsum = v0 + v1 + v2 + v3;
    int lane = t & 31, w = t >> 5;
    int x = tsum;
#pragma unroll
    for (int d = 1; d < 32; d <<= 1) {
        int y = __shfl_up_sync(0xffffffffu, x, d);
        if (lane >= d) x += y;
    }
    if (lane == 31) wsum[w] = x;
    __syncthreads();
    if (t < 32) {
        int y = wsum[t];
#pragma unroll
        for (int d = 1; d < 32; d <<= 1) {
            int z = __shfl_up_sync(0xffffffffu, y, d);
            if (t >= d) y += z;
        }
        wsum[t] = y;
    }
    __syncthreads();
    int woff = (w == 0) ? 0 : wsum[w - 1];
    int ex = woff + x - tsum;
    if (base + 0 < NSEG) g_scan[base + 0] = ex;
    ex += v0;
    if (base + 1 < NSEG) g_scan[base + 1] = ex;
    ex += v1;
    if (base + 2 < NSEG) g_scan[base + 2] = ex;
    ex += v2;
    if (base + 3 < NSEG) g_scan[base + 3] = ex;
    if (t == 0) g_bsum[b] = wsum[31];
}

// Exclusive scan of the NB2 block sums (single block of 256).
__global__ void scan_block_kernel() {
    __shared__ int wsum[8];
    int t = threadIdx.x;
    int v = (t < NB2) ? g_bsum[t] : 0;
    int lane = t & 31, w = t >> 5;
    int x = v;
#pragma unroll
    for (int d = 1; d < 32; d <<= 1) {
        int y = __shfl_up_sync(0xffffffffu, x, d);
        if (lane >= d) x += y;
    }
    if (lane == 31) wsum[w] = x;
    __syncthreads();
    if (t < 8) {
        int y = wsum[t];
#pragma unroll
        for (int d = 1; d < 8; d <<= 1) {
            int z = __shfl_up_sync(0xffu, y, d, 8);
            if (t >= d) y += z;
        }
        wsum[t] = y;
    }
    __syncthreads();
    int woff = (w == 0) ? 0 : wsum[w - 1];
    if (t < NB2) g_boff[t] = woff + x - v;
}

__global__ void scan_finish_kernel() {
    int i = blockIdx.x * blockDim.x + threadIdx.x;
    if (i < NSEG) {
        int r = g_scan[i] + g_boff[i >> 12];
        g_rp2[i] = r;
        g_cur[i] = r;
    }
    if (i == 0) g_rp2[NSEG] = NNZ_E;
}

__global__ void scatter_kernel(const int* __restrict__ rows,
                               const int* __restrict__ cols,
                               const float* __restrict__ vals) {
    int e = blockIdx.x * blockDim.x + threadIdx.x;
    if (e >= NNZ_E) return;
    int r = __ldg(rows + e);
    int c = __ldg(cols + e);
    float v = __ldg(vals + e);
    int t = (c >= TSPLIT);
    int pos = atomicAdd(&g_cur[r * NTILES + t], 1);
    g_csv[pos] = make_int2(c, __float_as_int(v));
}

// ---------------------------------------------------------------------------
// SpMM pass over column tile 0 (cols < TSPLIT): half-warp per row, exclusive
// ownership, write-only into g_side (streaming stores). Ego slice pinned
// evict_last; edge stream evict-first.
// ---------------------------------------------------------------------------
__global__ void __launch_bounds__(256)
spmm_pass_kernel(int pp) {
    int gtid = blockIdx.x * blockDim.x + threadIdx.x;
    int r = gtid >> 4;
    if (r >= NTOT) return;
    int j = threadIdx.x & 15;
    unsigned hmask = 0xFFFFu << (threadIdx.x & 16);
    unsigned long long pol = mk_evict_last();

    const float4* x4 = (const float4*)g_ego[pp];
    float4* side4 = (float4*)g_side;

    int s = __ldg(g_rp2 + r * NTILES);
    int e = __ldg(g_rp2 + r * NTILES + 1);

    float4 acc = make_float4(0.f, 0.f, 0.f, 0.f);
    for (int p = s; p < e; p += 16) {
        int idx = p + j;
        int cj = -1; float vj = 0.f;
        if (idx < e) {
            int2 cv = __ldcs(g_csv + idx);
            cj = cv.x; vj = __int_as_float(cv.y);
        }
#pragma unroll
        for (int q = 0; q < 16; q++) {
            int cc   = __shfl_sync(hmask, cj, q, 16);
            float vv = __shfl_sync(hmask, vj, q, 16);
            if (cc >= 0) {
                float4 g4 = ldg_el(x4 + (size_t)cc * 16 + j, pol);
                acc.x += vv * g4.x;
                acc.y += vv * g4.y;
                acc.z += vv * g4.z;
                acc.w += vv * g4.w;
            }
        }
    }
    __stcs(side4 + (size_t)r * 16 + j, acc);
}

// ---------------------------------------------------------------------------
// Fused: tile-1 SpMM (seeded with g_side partial) -> smem tiles ->
// GC/Bi GEMM + lrelu + row-L2-normalize -> out columns + next ego.
// ---------------------------------------------------------------------------
__global__ void __launch_bounds__(256)
fused_layer_kernel(const float* __restrict__ gw,
                   const float* __restrict__ gb,
                   const float* __restrict__ bw,
                   const float* __restrict__ bb,
                   float* __restrict__ out,
                   int col_off, int pp) {
    extern __shared__ float sh[];
    float* s_wgc  = sh;                 // 4096: wT[k*64+d]
    float* s_wbi  = sh + 4096;          // 4096
    float* s_side = sh + 8192;          // 64*68
    float* s_prod = sh + 8192 + 4352;   // 64*68 (reused as e-buffer)

    const float*  ego = g_ego[pp];
    float*   ego_next = g_ego[pp ^ 1];
    const float4* x4  = (const float4*)ego;
    const float4* side4 = (const float4*)g_side;

    int t = threadIdx.x;
    int j = t & 15;
    int h = t >> 4;
    unsigned hmask = 0xFFFFu << (t & 16);
    unsigned long long pol = mk_evict_last();

    for (int idx = t; idx < 4096; idx += 256) {
        int d = idx & 63, k = idx >> 6;
        s_wgc[k * 64 + d] = gw[d * 64 + k];
        s_wbi[k * 64 + d] = bw[d * 64 + k];
    }

    const int d0 = (t & 15) * 4;
    const int n0 = (t >> 4) * 4;
    float bg[4], bbv[4];
#pragma unroll
    for (int q = 0; q < 4; q++) {
        bg[q]  = __ldg(gb + d0 + q);
        bbv[q] = __ldg(bb + d0 + q);
    }

    for (int c = blockIdx.x; c < CHUNKS; c += gridDim.x) {
        __syncthreads();
        int base = c * 64;

        // ---- Phase 1: tile-1 SpMM seeded with side partial ----
#pragma unroll
        for (int i = 0; i < 4; i++) {
            int r = base + h * 4 + i;
            int s = __ldg(g_rp2 + r * NTILES + 1);
            int e = __ldg(g_rp2 + r * NTILES + 2);
            float4 acc = __ldcs(side4 + (size_t)r * 16 + j);
            for (int p = s; p < e; p += 16) {
                int idx = p + j;
                int cj = -1; float vj = 0.f;
                if (idx < e) {
                    int2 cv = __ldcs(g_csv + idx);
                    cj = cv.x; vj = __int_as_float(cv.y);
                }
#pragma unroll
                for (int q = 0; q < 16; q++) {
                    int cc   = __shfl_sync(hmask, cj, q, 16);
                    float vv = __shfl_sync(hmask, vj, q, 16);
                    if (cc >= 0) {
                        float4 g4 = ldg_el(x4 + (size_t)cc * 16 + j, pol);
                        acc.x += vv * g4.x;
                        acc.y += vv * g4.y;
                        acc.z += vv * g4.z;
                        acc.w += vv * g4.w;
                    }
                }
            }
            float4 ev = __ldg(x4 + (size_t)r * 16 + j);
            int node = h * 4 + i;
            *(float4*)&s_side[node * 68 + j * 4] = acc;
            *(float4*)&s_prod[node * 68 + j * 4] =
                make_float4(acc.x * ev.x, acc.y * ev.y, acc.z * ev.z, acc.w * ev.w);
        }
        __syncthreads();

        // ---- Phase 2: dense GC/Bi GEMM (4 nodes x 4 dims per thread) ----
        float accg[4][4], accb[4][4];
#pragma unroll
        for (int i = 0; i < 4; i++)
#pragma unroll
            for (int q = 0; q < 4; q++) {
                accg[i][q] = bg[q];
                accb[i][q] = bbv[q];
            }

#pragma unroll 8
        for (int k = 0; k < 64; k++) {
            float4 wg = *(const float4*)&s_wgc[k * 64 + d0];
            float4 wb = *(const float4*)&s_wbi[k * 64 + d0];
            float sv[4], pv[4];
#pragma unroll
            for (int i = 0; i < 4; i++) {
                sv[i] = s_side[(n0 + i) * 68 + k];
                pv[i] = s_prod[(n0 + i) * 68 + k];
            }
#pragma unroll
            for (int i = 0; i < 4; i++) {
                accg[i][0] += sv[i] * wg.x;
                accg[i][1] += sv[i] * wg.y;
                accg[i][2] += sv[i] * wg.z;
                accg[i][3] += sv[i] * wg.w;
                accb[i][0] += pv[i] * wb.x;
                accb[i][1] += pv[i] * wb.y;
                accb[i][2] += pv[i] * wb.z;
                accb[i][3] += pv[i] * wb.w;
            }
        }
        __syncthreads();

        // e = lrelu(gc) + lrelu(bi) into smem (reuse s_prod)
#pragma unroll
        for (int i = 0; i < 4; i++)
#pragma unroll
            for (int q = 0; q < 4; q++) {
                float a = accg[i][q], b = accb[i][q];
                float e = fmaxf(a, 0.01f * a) + fmaxf(b, 0.01f * b);
                s_prod[(n0 + i) * 68 + d0 + q] = e;
            }
        __syncthreads();

        // Row norms + global writes: thread -> (node = t/4, quarter = t%4)
        int node = t >> 2, qq = t & 3;
        float ss = 0.f;
#pragma unroll
        for (int m = 0; m < 16; m++) {
            float v = s_prod[node * 68 + qq * 16 + m];
            ss += v * v;
        }
        ss += __shfl_xor_sync(0xffffffffu, ss, 1);
        ss += __shfl_xor_sync(0xffffffffu, ss, 2);
        float inv = 1.f / fmaxf(sqrtf(ss), 1e-12f);

        size_t gnode = (size_t)(base + node);
#pragma unroll
        for (int m = 0; m < 16; m += 4) {
            float4 v = *(const float4*)&s_prod[node * 68 + qq * 16 + m];
            *(float4*)&ego_next[gnode * 64 + qq * 16 + m] = v;
            float4 vn = make_float4(v.x * inv, v.y * inv, v.z * inv, v.w * inv);
            __stcs((float4*)&out[gnode * 256 + col_off + qq * 16 + m], vn);
        }
    }
}

// ---------------------------------------------------------------------------
extern "C" void kernel_launch(void* const* d_in, const int* in_sizes, int n_in,
                              void* d_out, int out_size) {
    const int*   rows = (const int*)d_in[0];
    const int*   cols = (const int*)d_in[1];
    const float* vals = (const float*)d_in[2];
    const float* ue   = (const float*)d_in[3];
    const float* ie   = (const float*)d_in[4];
    const float* gw   = (const float*)d_in[5];
    const float* gb   = (const float*)d_in[6];
    const float* bw   = (const float*)d_in[7];
    const float* bb   = (const float*)d_in[8];
    float* out = (float*)d_out;

    const int smem_bytes = (4096 * 2 + 4352 * 2) * 4;  // 67584 B
    cudaFuncSetAttribute(fused_layer_kernel,
                         cudaFuncAttributeMaxDynamicSharedMemorySize, smem_bytes);

    init_kernel<<<(NTOT * DIM + 255) / 256, 256>>>(ue, ie, out);

    // ---- (row, col-tile)-sorted edge list build (once; reused by all layers) ----
    zero_cnt_kernel<<<(NSEG + 255) / 256, 256>>>();
    hist_kernel<<<(NNZ_E + 255) / 256, 256>>>(rows, cols);
    scan_local_kernel<<<NB2, 1024>>>();
    scan_block_kernel<<<1, 256>>>();
    scan_finish_kernel<<<(NSEG + 255) / 256, 256>>>();
    scatter_kernel<<<(NNZ_E + 255) / 256, 256>>>(rows, cols, vals);

    // ---- 3 layers: tile-0 pass + fused(tile-1 + dense) ----
    const int pass_blocks = (NTOT * 16 + 255) / 256;  // one half-warp per row
    for (int i = 0; i < NLAYERS; i++) {
        int pp = i & 1;
        spmm_pass_kernel<<<pass_blocks, 256>>>(pp);
        fused_layer_kernel<<<CHUNKS, 256, smem_bytes>>>(
            gw + i * 4096, gb + i * 64, bw + i * 4096, bb + i * 64,
            out, (i + 1) * 64, pp);
    }
}